// round 14
// baseline (speedup 1.0000x reference)
#include <cuda_runtime.h>
#include <cstdint>

// Shapes fixed by the reference
#define NB   4
#define DB   8
#define CB   3
#define RB   4
#define KK   5
#define HH   128
#define WW   128
#define HWSZ (HH * WW)
#define TH   2                          // rows per block (full 128-wide)
#define BROWS (TH + 4)                  // 6
#define BCOLS (WW + 4)                  // 132
#define TILE_FLOATS (CB * BROWS * BCOLS)  // 2376

// i-row chunk: 20 planes (q = r*5+j) x 2 rows x 128 w = 5120 floats (20 KB)
#define STAGE_FLOATS 5120
#define NUNITS (STAGE_FLOATS / 4)       // 1280 x 16B units
#define SMEM_FLOATS (2 * STAGE_FLOATS + TILE_FLOATS)   // 12616 -> 50464 B

__device__ __forceinline__ void cp16(uint32_t dst, const float* src) {
    asm volatile("cp.async.cg.shared.global [%0], [%1], 16;"
                 :: "r"(dst), "l"(src) : "memory");
}
__device__ __forceinline__ void cp_commit() {
    asm volatile("cp.async.commit_group;" ::: "memory");
}
template <int N>
__device__ __forceinline__ void cp_wait() {
    asm volatile("cp.async.wait_group %0;" :: "n"(N) : "memory");
}

// Block (128,2,2): x = pixel col (full width), si = r-group, tz = row.
// 512 threads, 4 CTAs/SM (2048 thr/SM, same residency as v8).
// Key change vs v8: per plane-row DRAM read is 512B CONTIGUOUS (was 128B).
__global__ __launch_bounds__(512, 4)
void adaptive_conv_ps_v12(const float* __restrict__ burst,
                          const float* __restrict__ kernels,
                          float* __restrict__ out)
{
    extern __shared__ float smem[];
    float* sb = smem + 2 * STAGE_FLOATS;          // burst tile [CB][BROWS][BCOLS]
    const uint32_t smem_u32 = (uint32_t)__cvta_generic_to_shared(smem);

    const int nd = blockIdx.z;                    // 0..31
    const int h0 = blockIdx.y * TH;               // 0..126
    const int x  = threadIdx.x;                   // 0..127
    const int si = threadIdx.y;                   // 0..1
    const int tz = threadIdx.z;                   // 0..1
    const int tid = (tz * 2 + si) * 128 + x;      // 0..511

    const float* kbase = kernels + (size_t)nd * (RB * KK * KK) * HWSZ;

    // ---- per-thread cp.async units: u = q*64 + row*32 + seg (16B seg) ----
    // plane q = r*5+j (q in 0..19); global plane = r*25 + i*5 + j
    int goff[3];                                  // float offsets, i-term excluded
    int soff[3];                                  // byte offsets within a stage
    #pragma unroll
    for (int k = 0; k < 3; k++) {
        int u   = tid + k * 512;
        int q   = u >> 6;
        int row = (u >> 5) & 1;
        int seg = u & 31;
        int r = q / 5, j = q - 5 * r;
        goff[k] = (r * 25 + j) * HWSZ + (h0 + row) * WW + seg * 4;
        soff[k] = u * 16;
    }
    const bool has3 = (tid < NUNITS - 1024);      // tid < 256

    // ---- prologue: issue chunks 0 and 1 ----
    #pragma unroll
    for (int c = 0; c < 2; c++) {
        const uint32_t stg = smem_u32 + c * (STAGE_FLOATS * 4);
        cp16(stg + soff[0], kbase + goff[0] + c * (5 * HWSZ));
        cp16(stg + soff[1], kbase + goff[1] + c * (5 * HWSZ));
        if (has3)
            cp16(stg + soff[2], kbase + goff[2] + c * (5 * HWSZ));
        cp_commit();
    }

    // ---- stage burst tile (3 ch, rows h0-2..h0+3, cols -2..129, zero-pad) ----
    const float* bptr = burst + (size_t)nd * CB * HWSZ;
    #pragma unroll
    for (int k = 0; k < 5; k++) {
        int idx = tid + k * 512;
        if (idx < TILE_FLOATS) {
            int c   = idx / (BROWS * BCOLS);
            int rem = idx - c * (BROWS * BCOLS);
            int row = rem / BCOLS;
            int col = rem - row * BCOLS;
            int gh  = h0 + row - 2;
            int gw  = col - 2;
            float v = 0.0f;
            if (gh >= 0 && gh < HH && gw >= 0 && gw < WW)
                v = bptr[c * HWSZ + gh * WW + gw];
            sb[idx] = v;
        }
    }
    __syncthreads();

    float a00 = 0.f, a01 = 0.f;
    float a10 = 0.f, a11 = 0.f;
    float a20 = 0.f, a21 = 0.f;

    // ---- v8 pipeline: wait<1>, sync, compute, sync, refill i+2 ----
    #pragma unroll
    for (int i = 0; i < KK; i++) {
        if (i < 4) cp_wait<1>(); else cp_wait<0>();
        __syncthreads();                          // chunk i visible block-wide

        const float* st  = smem + (i & 1) * STAGE_FLOATS + tz * WW + x;
        const float* b0p = sb + (0 * BROWS + tz + i) * BCOLS + x;
        const float* b1p = sb + (1 * BROWS + tz + i) * BCOLS + x;
        const float* b2p = sb + (2 * BROWS + tz + i) * BCOLS + x;
        #pragma unroll
        for (int j = 0; j < KK; j++) {
            const float k0 = st[(10 * si + j)     * (TH * WW)];
            const float k1 = st[(10 * si + 5 + j) * (TH * WW)];
            const float b0 = b0p[j];
            const float b1 = b1p[j];
            const float b2 = b2p[j];
            a00 = fmaf(k0, b0, a00);  a01 = fmaf(k1, b0, a01);
            a10 = fmaf(k0, b1, a10);  a11 = fmaf(k1, b1, a11);
            a20 = fmaf(k0, b2, a20);  a21 = fmaf(k1, b2, a21);
        }
        __syncthreads();                          // stage free for refill

        if (i + 2 < KK) {
            const uint32_t stg = smem_u32 + (i & 1) * (STAGE_FLOATS * 4);
            const int ioff = (i + 2) * (5 * HWSZ);
            cp16(stg + soff[0], kbase + goff[0] + ioff);
            cp16(stg + soff[1], kbase + goff[1] + ioff);
            if (has3)
                cp16(stg + soff[2], kbase + goff[2] + ioff);
            cp_commit();
        }
    }

    // ---- fused pixel shuffle: out (nd, c, 2H, 2W); row 2h+si, cols 2x..2x+1 ----
    const int h = h0 + tz;
    float2* o2 = reinterpret_cast<float2*>(out);
    const size_t rowbase = ((size_t)nd * CB) * (2 * HH) + (2 * h + si);
    __stcs(&o2[(rowbase + 0 * 2 * HH) * WW + x], make_float2(a00, a01));
    __stcs(&o2[(rowbase + 1 * 2 * HH) * WW + x], make_float2(a10, a11));
    __stcs(&o2[(rowbase + 2 * 2 * HH) * WW + x], make_float2(a20, a21));
}

extern "C" void kernel_launch(void* const* d_in, const int* in_sizes, int n_in,
                              void* d_out, int out_size)
{
    const float* burst   = (const float*)d_in[0];   // (4,8,3,128,128)
    const float* kernels = (const float*)d_in[1];   // (4,8,4,5,5,128,128)
    float* out = (float*)d_out;                     // (4,8,3,256,256)

    static bool attr_set = false;
    if (!attr_set) {
        cudaFuncSetAttribute(adaptive_conv_ps_v12,
                             cudaFuncAttributeMaxDynamicSharedMemorySize,
                             SMEM_FLOATS * 4);
        attr_set = true;
    }

    dim3 block(128, 2, 2);                          // 512 threads
    dim3 grid(1, HH / TH, NB * DB);                 // (1, 64, 32) = 2048 blocks
    adaptive_conv_ps_v12<<<grid, block, SMEM_FLOATS * 4>>>(burst, kernels, out);
}

// round 15
// speedup vs baseline: 1.0556x; 1.0556x over previous
#include <cuda_runtime.h>

// Shapes fixed by the reference
#define NB   4
#define DB   8
#define CB   3
#define RB   4
#define KK   5
#define HH   128
#define WW   128
#define HWSZ (HH * WW)
#define TWP  32                     // px-pairs per tile row -> 64 px wide
#define TH   4                      // tile height
#define SH_  (TH + 4)               // 8
#define SW_  (2 * TWP + 4)          // 68
#define TILE_FLOATS (CB * SH_ * SW_)   // 1632

// Block (32,2,4): tx = px-pair, si = r-group, tz = row. 256 threads, 5 CTAs/SM.
// Thread: 2 adjacent px x 1 si-group (r=2si,2si+1) x 3 ch = 12 accumulators.
__global__ __launch_bounds__(256, 5)
void adaptive_conv_ps_v13(const float* __restrict__ burst,
                          const float* __restrict__ kernels,
                          float* __restrict__ out)
{
    __shared__ alignas(16) float s[CB][SH_][SW_];

    const int nd = blockIdx.z;                 // 0..31
    const int h0 = blockIdx.y * TH;
    const int w0 = blockIdx.x * (2 * TWP);     // 0 or 64
    const int tx = threadIdx.x;                // 0..31 -> px (w0+2tx, w0+2tx+1)
    const int si = threadIdx.y;                // 0..1
    const int tz = threadIdx.z;                // 0..3
    const int tid = (tz * 2 + si) * 32 + tx;

    // ---- stage burst tile (3 ch, halo 2, zero-pad OOB): 1632 elems ----
    const float* bptr = burst + (size_t)nd * CB * HWSZ;
    #pragma unroll
    for (int k = 0; k < 7; k++) {
        int idx = tid + k * 256;
        if (idx < TILE_FLOATS) {
            int c   = idx / (SH_ * SW_);
            int rem = idx - c * (SH_ * SW_);
            int sh  = rem / SW_;
            int sw  = rem - sh * SW_;
            int gh  = h0 + sh - 2;
            int gw  = w0 + sw - 2;
            float v = 0.0f;
            if (gh >= 0 && gh < HH && gw >= 0 && gw < WW)
                v = bptr[c * HWSZ + gh * WW + gw];
            s[c][sh][sw] = v;
        }
    }
    __syncthreads();

    const int h = h0 + tz;
    const int w = w0 + 2 * tx;                 // first pixel of the pair

    float a[CB][2][2];                         // [c][sj][px]
    #pragma unroll
    for (int c = 0; c < CB; c++)
        #pragma unroll
        for (int q = 0; q < 2; q++) { a[c][q][0] = 0.f; a[c][q][1] = 0.f; }

    // kernels: (nd, r, i, j, h, w); r = 2si (k0) and 2si+1 (k1), float2 at px pair
    const float2* kp = reinterpret_cast<const float2*>(
        kernels + ((size_t)nd * (RB * KK * KK) + (size_t)si * (2 * KK * KK)) * HWSZ
                + (size_t)h * WW) + (w >> 1);
    const int PLANE2 = HWSZ / 2;

    #pragma unroll
    for (int i = 0; i < KK; i++) {
        // burst window: cols 2tx..2tx+5 (halo-relative), 3 aligned LDS.64 per channel
        float bw[CB][6];
        #pragma unroll
        for (int c = 0; c < CB; c++) {
            const float* row = &s[c][tz + i][2 * tx];
            #pragma unroll
            for (int q = 0; q < 3; q++) {
                float2 t = *reinterpret_cast<const float2*>(row + 2 * q);
                bw[c][2 * q] = t.x; bw[c][2 * q + 1] = t.y;
            }
        }
        #pragma unroll
        for (int j = 0; j < KK; j++) {
            const int t = i * KK + j;
            const float2 k0 = __ldcs(kp + (size_t)t * PLANE2);
            const float2 k1 = __ldcs(kp + (size_t)(t + KK * KK) * PLANE2);
            #pragma unroll
            for (int c = 0; c < CB; c++) {
                a[c][0][0] = fmaf(k0.x, bw[c][j + 0], a[c][0][0]);
                a[c][0][1] = fmaf(k0.y, bw[c][j + 1], a[c][0][1]);
                a[c][1][0] = fmaf(k1.x, bw[c][j + 0], a[c][1][0]);
                a[c][1][1] = fmaf(k1.y, bw[c][j + 1], a[c][1][1]);
            }
        }
    }

    // ---- fused pixel shuffle: out (nd, c, 2H, 2W) ----
    // px pair (w, w+1), r = si*2+sj -> row 2h+si, cols 2w..2w+3: one STG.128 per (c,si)
    float4* o4 = reinterpret_cast<float4*>(out);
    const int orow = 2 * h + si;
    #pragma unroll
    for (int c = 0; c < CB; c++) {
        const size_t row = (size_t)(nd * CB + c) * (2 * HH) + orow;
        __stcs(&o4[row * (2 * WW / 4) + (w >> 1)],
               make_float4(a[c][0][0], a[c][1][0], a[c][0][1], a[c][1][1]));
    }
}

extern "C" void kernel_launch(void* const* d_in, const int* in_sizes, int n_in,
                              void* d_out, int out_size)
{
    const float* burst   = (const float*)d_in[0];   // (4,8,3,128,128)
    const float* kernels = (const float*)d_in[1];   // (4,8,4,5,5,128,128)
    float* out = (float*)d_out;                     // (4,8,3,256,256)

    dim3 block(32, 2, 4);                           // 256 threads
    dim3 grid(WW / (2 * TWP), HH / TH, NB * DB);    // (2, 32, 32) = 2048 blocks
    adaptive_conv_ps_v13<<<grid, block>>>(burst, kernels, out);
}